// round 13
// baseline (speedup 1.0000x reference)
#include <cuda_runtime.h>
#include <cuda_bf16.h>
#include <cstdint>

// Problem constants
#define VV   32000
#define EE   256
#define HLL  1024
#define HCC  256
#define BB   512
#define TST  100
#define DSPL 4        // dec split-K factor
#define NBT  250      // logits n-blocks (32000/128)

// ---------------- scratch (__device__ globals, no allocation) ----------------
__device__ float g_h[BB * HLL];
__device__ float g_gi[BB * 3 * HLL];
__device__ float g_gh[BB * 3 * HLL];
__device__ float g_gictx[BB * 3 * HLL];
__device__ float g_dec[BB * EE];
__device__ float g_decpart[DSPL * BB * EE];
__device__ __nv_bfloat16 g_e0[(size_t)VV * EE];
__device__ __nv_bfloat16 g_e1[(size_t)VV * EE];
__device__ __nv_bfloat16 g_e2[(size_t)VV * EE];
__device__ __nv_bfloat16 g_a0[BB * EE];
__device__ __nv_bfloat16 g_a1[BB * EE];
__device__ __nv_bfloat16 g_a2[BB * EE];
__device__ float g_candv[BB * NBT];
__device__ int   g_candi[BB * NBT];
__device__ int   g_tok[BB];

// ---------------- threefry2x32 ----------------
__host__ __device__ __forceinline__ unsigned int rotl32(unsigned int x, int r) {
    return (x << r) | (x >> (32 - r));
}
__host__ __device__ __forceinline__ void threefry2x32(
    unsigned int k0, unsigned int k1, unsigned int& x0, unsigned int& x1)
{
    unsigned int ks2 = k0 ^ k1 ^ 0x1BD11BDAu;
    x0 += k0; x1 += k1;
#define TF_R(r) { x0 += x1; x1 = rotl32(x1, (r)); x1 ^= x0; }
    TF_R(13) TF_R(15) TF_R(26) TF_R(6)   x0 += k1;  x1 += ks2 + 1u;
    TF_R(17) TF_R(29) TF_R(16) TF_R(24)  x0 += ks2; x1 += k0  + 2u;
    TF_R(13) TF_R(15) TF_R(26) TF_R(6)   x0 += k0;  x1 += k1  + 3u;
    TF_R(17) TF_R(29) TF_R(16) TF_R(24)  x0 += k1;  x1 += ks2 + 4u;
    TF_R(13) TF_R(15) TF_R(26) TF_R(6)   x0 += ks2; x1 += k0  + 5u;
#undef TF_R
}

// ---------------- flag-proof transcendentals ----------------
__device__ __forceinline__ float acc_logf(float a) {
    int e = (__float_as_int(a) - 0x3f2aaaab) & 0xff800000;
    float m = __int_as_float(__float_as_int(a) - e);
    float i = (float)e * 1.19209290e-7f;
    float f = m - 1.0f;
    float s = f * f;
    float r = fmaf(0.230836749f, f, -0.279208571f);
    float t = fmaf(0.331826031f, f, -0.498910338f);
    r = fmaf(r, s, t);
    r = fmaf(r, s, f);
    r = fmaf(i, 0.693147182f, r);
    return r;
}
__device__ __forceinline__ float acc_expf(float a) {
    float j = fmaf(1.442695041f, a, 12582912.0f) - 12582912.0f;
    float f = fmaf(j, -6.93145752e-1f, a);
    f = fmaf(j, -1.42860677e-6f, f);
    float r = 1.37805939e-3f;
    r = fmaf(r, f, 8.37312452e-3f);
    r = fmaf(r, f, 4.16695364e-2f);
    r = fmaf(r, f, 1.66664720e-1f);
    r = fmaf(r, f, 4.99999851e-1f);
    r = fmaf(r, f, 1.0f);
    r = fmaf(r, f, 1.0f);
    int i = (int)j;
    return r * __int_as_float((127 + i) << 23);
}
__device__ __forceinline__ float acc_sigmoid(float x) { return 1.0f / (1.0f + acc_expf(-x)); }
__device__ __forceinline__ float acc_tanh(float x) {
    float t = acc_expf(2.0f * x);
    return (t - 1.0f) / (t + 1.0f);
}
__device__ __forceinline__ float gumbel_from_bits(unsigned int bits) {
    float f = __uint_as_float((bits >> 9) | 0x3f800000u) - 1.0f;
    const float TINY = 1.17549435e-38f;
    float u = fmaxf(TINY, f + TINY);
    return -acc_logf(-acc_logf(u));
}

// ---------------- base-ISA MMA helpers (no tcgen05!) ------------------------
__device__ __forceinline__ uint32_t smem_to_u32(const void* p) {
    uint32_t a;
    asm("{ .reg .u64 t; cvta.to.shared.u64 t, %1; cvt.u32.u64 %0, t; }" : "=r"(a) : "l"(p));
    return a;
}
__device__ __forceinline__ void ldsm_x4(uint32_t& r0, uint32_t& r1,
                                        uint32_t& r2, uint32_t& r3, uint32_t addr)
{
    asm volatile("ldmatrix.sync.aligned.m8n8.x4.shared.b16 {%0,%1,%2,%3}, [%4];"
                 : "=r"(r0), "=r"(r1), "=r"(r2), "=r"(r3) : "r"(addr));
}
__device__ __forceinline__ void mma16816(float* d, const uint32_t* a,
                                         uint32_t b0, uint32_t b1)
{
    asm volatile(
        "mma.sync.aligned.m16n8k16.row.col.f32.bf16.bf16.f32 "
        "{%0,%1,%2,%3}, {%4,%5,%6,%7}, {%8,%9}, {%0,%1,%2,%3};"
        : "+f"(d[0]), "+f"(d[1]), "+f"(d[2]), "+f"(d[3])
        : "r"(a[0]), "r"(a[1]), "r"(a[2]), "r"(a[3]), "r"(b0), "r"(b1));
}

// ---------------- init ----------------
__global__ void init_kernel(const float* __restrict__ lang_h0,
                            const int* __restrict__ inpt0,
                            float* __restrict__ out)
{
    int idx = blockIdx.x * blockDim.x + threadIdx.x;
    if (idx < BB * HLL) {
        float v = lang_h0[idx];
        g_h[idx] = v;
        out[(size_t)TST * BB + idx] = v;
    }
    if (idx < BB) g_tok[idx] = inpt0[idx];
}

// ---------------- bf16 3-way splits -----------------------------------------
__global__ void emb_split(const float* __restrict__ emb)
{
    size_t idx = (size_t)blockIdx.x * blockDim.x + threadIdx.x;  // VV*EE
    float v = emb[idx];
    __nv_bfloat16 h0 = __float2bfloat16(v);
    float r = v - __bfloat162float(h0);
    __nv_bfloat16 h1 = __float2bfloat16(r);
    float r2 = r - __bfloat162float(h1);
    g_e0[idx] = h0; g_e1[idx] = h1; g_e2[idx] = __float2bfloat16(r2);
}
__global__ void dec_split(const float* __restrict__ dec)
{
    int idx = blockIdx.x * blockDim.x + threadIdx.x;  // BB*EE
    float v = dec[idx];
    __nv_bfloat16 h0 = __float2bfloat16(v);
    float r = v - __bfloat162float(h0);
    __nv_bfloat16 h1 = __float2bfloat16(r);
    float r2 = r - __bfloat162float(h1);
    g_a0[idx] = h0; g_a1[idx] = h1; g_a2[idx] = __float2bfloat16(r2);
}

// ============================================================================
// 64x64x16 double-buffered SGEMM core (FFMA; gates/dec/gictx)
// ============================================================================
#define GEMM64_BODY(A, LDA, AROW, BM, LDB, C, LDC, K, BIAS, ADDM, LDADD, M0, N0) \
{                                                                              \
    __shared__ float As[2][16 * 68];                                           \
    __shared__ float Bs[2][16 * 68];                                           \
    int tid = threadIdx.x;                                                     \
    int tx = tid & 15, ty = tid >> 4;                                          \
    int lr = tid >> 2;                                                         \
    int lk = (tid & 3) * 4;                                                    \
    int am_ = (AROW) ? (AROW)[(M0) + lr] : ((M0) + lr);                        \
    const float* aptr = (A) + (size_t)am_ * (LDA) + lk;                        \
    const float* bptr = (BM) + (size_t)((N0) + lr) * (LDB) + lk;               \
    float4 ra = *(const float4*)aptr;                                          \
    float4 rb = *(const float4*)bptr;                                          \
    As[0][(lk + 0) * 68 + lr] = ra.x; As[0][(lk + 1) * 68 + lr] = ra.y;        \
    As[0][(lk + 2) * 68 + lr] = ra.z; As[0][(lk + 3) * 68 + lr] = ra.w;        \
    Bs[0][(lk + 0) * 68 + lr] = rb.x; Bs[0][(lk + 1) * 68 + lr] = rb.y;        \
    Bs[0][(lk + 2) * 68 + lr] = rb.z; Bs[0][(lk + 3) * 68 + lr] = rb.w;        \
    __syncthreads();                                                           \
    float acc[4][4] = {};                                                      \
    int nkt = (K) / 16;                                                        \
    for (int kt = 0; kt < nkt; ++kt) {                                         \
        int cur = kt & 1;                                                      \
        if (kt + 1 < nkt) {                                                    \
            ra = *(const float4*)(aptr + (kt + 1) * 16);                       \
            rb = *(const float4*)(bptr + (kt + 1) * 16);                       \
        }                                                                      \
        _Pragma("unroll")                                                      \
        for (int k = 0; k < 16; ++k) {                                         \
            float4 a = *(const float4*)&As[cur][k * 68 + ty * 4];              \
            float4 b = *(const float4*)&Bs[cur][k * 68 + tx * 4];              \
            float av[4] = {a.x, a.y, a.z, a.w};                                \
            float bv[4] = {b.x, b.y, b.z, b.w};                                \
            _Pragma("unroll")                                                  \
            for (int i = 0; i < 4; ++i)                                        \
                _Pragma("unroll")                                              \
                for (int j = 0; j < 4; ++j)                                    \
                    acc[i][j] = fmaf(av[i], bv[j], acc[i][j]);                 \
        }                                                                      \
        if (kt + 1 < nkt) {                                                    \
            int nxt = cur ^ 1;                                                 \
            As[nxt][(lk + 0) * 68 + lr] = ra.x; As[nxt][(lk + 1) * 68 + lr] = ra.y; \
            As[nxt][(lk + 2) * 68 + lr] = ra.z; As[nxt][(lk + 3) * 68 + lr] = ra.w; \
            Bs[nxt][(lk + 0) * 68 + lr] = rb.x; Bs[nxt][(lk + 1) * 68 + lr] = rb.y; \
            Bs[nxt][(lk + 2) * 68 + lr] = rb.z; Bs[nxt][(lk + 3) * 68 + lr] = rb.w; \
        }                                                                      \
        __syncthreads();                                                       \
    }                                                                          \
    _Pragma("unroll")                                                          \
    for (int i = 0; i < 4; ++i) {                                              \
        int m = (M0) + ty * 4 + i;                                             \
        int n = (N0) + tx * 4;                                                 \
        float4 v = make_float4(acc[i][0], acc[i][1], acc[i][2], acc[i][3]);    \
        if (BIAS) {                                                            \
            float4 bb = *(const float4*)&(BIAS)[n];                            \
            v.x += bb.x; v.y += bb.y; v.z += bb.z; v.w += bb.w;                \
        }                                                                      \
        if (ADDM) {                                                            \
            float4 ad = *(const float4*)&(ADDM)[(size_t)m * (LDADD) + n];      \
            v.x += ad.x; v.y += ad.y; v.z += ad.z; v.w += ad.w;                \
        }                                                                      \
        *(float4*)&(C)[(size_t)m * (LDC) + n] = v;                             \
    }                                                                          \
}

__global__ void __launch_bounds__(256) gates_gemm(
    const float* __restrict__ word_emb, const int* __restrict__ tok,
    const float* __restrict__ w_ih, const float* __restrict__ gictx,
    float* __restrict__ gi,
    const float* __restrict__ h, const float* __restrict__ w_hh,
    const float* __restrict__ b_hh, float* __restrict__ gh)
{
    int m0 = blockIdx.y * 64, n0 = blockIdx.x * 64;
    if (blockIdx.z == 0) {
        GEMM64_BODY(word_emb, EE, tok, w_ih, (EE + HCC), gi, (3 * HLL), EE,
                    ((const float*)0), gictx, (3 * HLL), m0, n0);
    } else {
        GEMM64_BODY(h, HLL, ((const int*)0), w_hh, HLL, gh, (3 * HLL), HLL,
                    b_hh, ((const float*)0), 0, m0, n0);
    }
}

__global__ void __launch_bounds__(256) gictx_gemm(
    const float* __restrict__ ctx_h, const float* __restrict__ w_ih,
    const float* __restrict__ b_ih, float* __restrict__ gictx)
{
    int m0 = blockIdx.y * 64, n0 = blockIdx.x * 64;
    GEMM64_BODY(ctx_h, HCC, ((const int*)0), (w_ih + EE), (EE + HCC),
                gictx, (3 * HLL), HCC, b_ih, ((const float*)0), 0, m0, n0);
}

__global__ void __launch_bounds__(256) dec_part_gemm(
    const float* __restrict__ h, const float* __restrict__ dec_W,
    float* __restrict__ part)
{
    int m0 = blockIdx.y * 64, n0 = blockIdx.x * 64;
    int koff = blockIdx.z * (HLL / DSPL);
    const float* A = h + koff;
    const float* B = dec_W + koff;
    float* C = part + (size_t)blockIdx.z * BB * EE;
    GEMM64_BODY(A, HLL, ((const int*)0), B, HLL, C, EE, (HLL / DSPL),
                ((const float*)0), ((const float*)0), 0, m0, n0);
}

__global__ void dec_reduce(const float* __restrict__ part,
                           const float* __restrict__ dec_b,
                           float* __restrict__ dec)
{
    int idx = blockIdx.x * blockDim.x + threadIdx.x;
    float s = dec_b[idx & (EE - 1)];
#pragma unroll
    for (int z = 0; z < DSPL; ++z)
        s += part[(size_t)z * BB * EE + idx];
    dec[idx] = s;
}

// ============================================================================
// Logits via mma.sync bf16 (8-product split, fp32 accum) + fused sampler.
// Grid (250, 4): CTA tile M=128, N=128. 8 warps as 4(m) x 2(n), warp = 32x64.
// Virtual K = 8 segments x 256 (segment s: dec plane PA[s] x emb plane PB[s]).
// K-chunks of 32, double-buffered smem (80 B pitch -> ldmatrix conflict-free).
// ============================================================================
__global__ void __launch_bounds__(256, 2) logits_mma(
    unsigned int k0, unsigned int k1,
    float* __restrict__ candv, int* __restrict__ candi)
{
    __shared__ __nv_bfloat16 As[2][128 * 40];  // pitch 40 bf16 = 80 B (32 used)
    __shared__ __nv_bfloat16 Bs[2][128 * 40];
    __shared__ float scv[2][128];
    __shared__ int   sci[2][128];

    int tid = threadIdx.x;
    int lane = tid & 31;
    int wid = tid >> 5;
    int warpm = wid >> 1;          // 0..3 -> rows warpm*32
    int warpn = wid & 1;           // 0..1 -> cols warpn*64
    int m0g = blockIdx.y * 128;
    int n0g = blockIdx.x * 128;

    const __nv_bfloat16* aarr[3] = {g_a0, g_a1, g_a2};
    const __nv_bfloat16* barr[3] = {g_e0, g_e1, g_e2};
    const int PA[8] = {0, 1, 2, 0, 1, 2, 0, 1};
    const int PB[8] = {0, 0, 0, 1, 1, 1, 2, 2};

    // load coords: 2 x uint4 (16B) per thread per operand per chunk
    int lrow = tid >> 2;           // 0..63
    int lq = tid & 3;              // 16B chunk within 64B row

    float acc[2][8][4];
#pragma unroll
    for (int mt = 0; mt < 2; ++mt)
#pragma unroll
        for (int nt = 0; nt < 8; ++nt)
#pragma unroll
            for (int r = 0; r < 4; ++r) acc[mt][nt][r] = 0.0f;

    uint4 ra0, ra1, rb0, rb1;
    // preload chunk 0 (segment 0: a0 x e0, kk = 0)
    {
        const __nv_bfloat16* asrc = aarr[0] + (size_t)m0g * EE;
        const __nv_bfloat16* bsrc = barr[0] + (size_t)n0g * EE;
        ra0 = *(const uint4*)(asrc + (size_t)lrow * EE + lq * 8);
        ra1 = *(const uint4*)(asrc + (size_t)(lrow + 64) * EE + lq * 8);
        rb0 = *(const uint4*)(bsrc + (size_t)lrow * EE + lq * 8);
        rb1 = *(const uint4*)(bsrc + (size_t)(lrow + 64) * EE + lq * 8);
        *(uint4*)((char*)&As[0][0] + lrow * 80 + lq * 16) = ra0;
        *(uint4*)((char*)&As[0][0] + (lrow + 64) * 80 + lq * 16) = ra1;
        *(uint4*)((char*)&Bs[0][0] + lrow * 80 + lq * 16) = rb0;
        *(uint4*)((char*)&Bs[0][0] + (lrow + 64) * 80 + lq * 16) = rb1;
    }
    __syncthreads();

    for (int c = 0; c < 64; ++c) {
        int cur = c & 1;
        if (c + 1 < 64) {
            int seg = (c + 1) >> 3;
            int kk = ((c + 1) & 7) * 32;
            const __nv_bfloat16* asrc = aarr[PA[seg]] + (size_t)m0g * EE + kk;
            const __nv_bfloat16* bsrc = barr[PB[seg]] + (size_t)n0g * EE + kk;
            ra0 = *(const uint4*)(asrc + (size_t)lrow * EE + lq * 8);
            ra1 = *(const uint4*)(asrc + (size_t)(lrow + 64) * EE + lq * 8);
            rb0 = *(const uint4*)(bsrc + (size_t)lrow * EE + lq * 8);
            rb1 = *(const uint4*)(bsrc + (size_t)(lrow + 64) * EE + lq * 8);
        }

        uint32_t a_base = smem_to_u32(&As[cur][0]);
        uint32_t b_base = smem_to_u32(&Bs[cur][0]);
#pragma unroll
        for (int ks = 0; ks < 2; ++ks) {
            uint32_t af[2][4];
#pragma unroll
            for (int mt = 0; mt < 2; ++mt) {
                int row = warpm * 32 + mt * 16 + (lane & 15);
                uint32_t ad = a_base + row * 80 + ks * 32 + ((lane >> 4) * 16);
                ldsm_x4(af[mt][0], af[mt][1], af[mt][2], af[mt][3], ad);
            }
#pragma unroll
            for (int p = 0; p < 4; ++p) {
                int row = warpn * 64 + p * 16 + (lane & 15);
                uint32_t bd = b_base + row * 80 + ks * 32 + ((lane >> 4) * 16);
                uint32_t r0, r1, r2, r3;
                ldsm_x4(r0, r1, r2, r3, bd);
#pragma unroll
                for (int mt = 0; mt < 2; ++mt) {
                    mma16816(acc[mt][2 * p], af[mt], r0, r2);
                    mma16816(acc[mt][2 * p + 1], af[mt], r1, r3);
                }
            }
        }

        if (c + 1 < 64) {
            int nxt = cur ^ 1;
            *(uint4*)((char*)&As[nxt][0] + lrow * 80 + lq * 16) = ra0;
            *(uint4*)((char*)&As[nxt][0] + (lrow + 64) * 80 + lq * 16) = ra1;
            *(uint4*)((char*)&Bs[nxt][0] + lrow * 80 + lq * 16) = rb0;
            *(uint4*)((char*)&Bs[nxt][0] + (lrow + 64) * 80 + lq * 16) = rb1;
        }
        __syncthreads();
    }

    // ---- Epilogue: gumbel + argmax over register accumulators ----
    // Thread holds: rows m0g + warpm*32 + mt*16 + rr*8 + (lane>>2), mt,rr in {0,1}
    //               cols n0g + warpn*64 + nt*8 + (lane&3)*2 + jj
#pragma unroll
    for (int mt = 0; mt < 2; ++mt) {
#pragma unroll
        for (int rr = 0; rr < 2; ++rr) {
            int lrow_m = warpm * 32 + mt * 16 + rr * 8 + (lane >> 2);
            int gm = m0g + lrow_m;
            unsigned int jbase = (unsigned int)gm * (unsigned int)VV;
            float bv = -3.4e38f;
            int bn = 0;
#pragma unroll
            for (int nt = 0; nt < 8; ++nt) {
#pragma unroll
                for (int jj = 0; jj < 2; ++jj) {
                    int n = n0g + warpn * 64 + nt * 8 + (lane & 3) * 2 + jj;
                    unsigned int x0 = 0u;
                    unsigned int x1 = jbase + (unsigned int)n;
                    threefry2x32(k0, k1, x0, x1);
                    float cval = acc[mt][nt][rr * 2 + jj] + gumbel_from_bits(x0 ^ x1);
                    if (cval > bv) { bv = cval; bn = n; }  // ascending n per thread
                }
            }
            // reduce across the 4 lanes sharing this row (lane&3 groups)
#pragma unroll
            for (int s = 1; s < 4; s <<= 1) {
                float ov = __shfl_xor_sync(0xffffffffu, bv, s);
                int   on = __shfl_xor_sync(0xffffffffu, bn, s);
                if (ov > bv || (ov == bv && on < bn)) { bv = ov; bn = on; }
            }
            if ((lane & 3) == 0) {
                scv[warpn][lrow_m] = bv;
                sci[warpn][lrow_m] = bn;
            }
        }
    }
    __syncthreads();
    if (tid < 128) {
        float v0 = scv[0][tid], v1 = scv[1][tid];
        int   i0 = sci[0][tid], i1 = sci[1][tid];
        float vb; int ib;
        if (v1 > v0) { vb = v1; ib = i1; } else { vb = v0; ib = i0; }  // tie -> lower n (warpn 0)
        int gm = m0g + tid;
        candv[(size_t)gm * NBT + blockIdx.x] = vb;
        candi[(size_t)gm * NBT + blockIdx.x] = ib;
    }
}

// ---------------- final cross-block argmax -> token -------------------------
__global__ void __launch_bounds__(256) sample_reduce(
    const float* __restrict__ candv, const int* __restrict__ candi,
    int* __restrict__ tok, float* __restrict__ outtok)
{
    int b = blockIdx.x;
    int tid = threadIdx.x;
    float bv = -3.4e38f;
    int bn = 0x7fffffff;
    if (tid < NBT) {
        bv = candv[(size_t)b * NBT + tid];
        bn = candi[(size_t)b * NBT + tid];
    }
    __shared__ float sv[256];
    __shared__ int   si[256];
    sv[tid] = bv; si[tid] = bn;
    __syncthreads();
    for (int s = 128; s > 0; s >>= 1) {
        if (tid < s) {
            float v2 = sv[tid + s]; int i2 = si[tid + s];
            float v1 = sv[tid];     int i1 = si[tid];
            if (v2 > v1 || (v2 == v1 && i2 < i1)) { sv[tid] = v2; si[tid] = i2; }
        }
        __syncthreads();
    }
    if (tid == 0) {
        tok[b] = si[0];
        outtok[b] = (float)si[0];
    }
}

// ---------------- GRU elementwise ----------------
__global__ void gru_act(const float* __restrict__ gi, const float* __restrict__ gh,
                        float* __restrict__ h, float* __restrict__ hs_out)
{
    int idx = blockIdx.x * blockDim.x + threadIdx.x;
    int b = idx >> 10, j = idx & 1023;
    size_t base = (size_t)b * 3072 + j;
    float ir = gi[base], iz = gi[base + 1024], in_ = gi[base + 2048];
    float hr = gh[base], hz = gh[base + 1024], hn = gh[base + 2048];
    float r = acc_sigmoid(ir + hr);
    float z = acc_sigmoid(iz + hz);
    float n = acc_tanh(in_ + r * hn);
    float hprev = h[idx];
    float hnew = (1.0f - z) * n + z * hprev;
    h[idx] = hnew;
    hs_out[idx] = hnew;
}

// ---------------- host driver ----------------
extern "C" void kernel_launch(void* const* d_in, const int* in_sizes, int n_in,
                              void* d_out, int out_size)
{
    const float* lang_h0  = (const float*)d_in[0];
    const float* ctx_h    = (const float*)d_in[1];
    const float* word_emb = (const float*)d_in[2];
    const float* dec_W    = (const float*)d_in[3];
    const float* dec_b    = (const float*)d_in[4];
    const float* w_ih     = (const float*)d_in[5];
    const float* w_hh     = (const float*)d_in[6];
    const float* b_ih     = (const float*)d_in[7];
    const float* b_hh     = (const float*)d_in[8];
    const int*   inpt0    = (const int*)d_in[9];
    float* out = (float*)d_out;

    float *ph, *pgi, *pgh, *pgictx, *pdec, *pdecp, *pcandv;
    int *pcandi, *ptok;
    cudaGetSymbolAddress((void**)&ph, g_h);
    cudaGetSymbolAddress((void**)&pgi, g_gi);
    cudaGetSymbolAddress((void**)&pgh, g_gh);
    cudaGetSymbolAddress((void**)&pgictx, g_gictx);
    cudaGetSymbolAddress((void**)&pdec, g_dec);
    cudaGetSymbolAddress((void**)&pdecp, g_decpart);
    cudaGetSymbolAddress((void**)&pcandv, g_candv);
    cudaGetSymbolAddress((void**)&pcandi, g_candi);
    cudaGetSymbolAddress((void**)&ptok, g_tok);

    // PARTITIONABLE key schedule: key_t = threefry2x32(key=(0,1), 0, t)
    unsigned int kk0[TST], kk1[TST];
    for (int t = 0; t < TST; ++t) {
        unsigned int x0 = 0u, x1 = (unsigned int)t;
        threefry2x32(0u, 1u, x0, x1);
        kk0[t] = x0;
        kk1[t] = x1;
    }

    init_kernel<<<2048, 256>>>(lang_h0, inpt0, out);
    emb_split<<<VV * EE / 256, 256>>>(word_emb);
    gictx_gemm<<<dim3(48, 8), 256>>>(ctx_h, w_ih, b_ih, pgictx);

    float* hsbase = out + (size_t)TST * BB;

    for (int t = 0; t < TST; ++t) {
        gates_gemm<<<dim3(48, 8, 2), 256>>>(word_emb, ptok, w_ih, pgictx, pgi,
                                            ph, w_hh, b_hh, pgh);
        gru_act<<<2048, 256>>>(pgi, pgh, ph,
                               hsbase + (size_t)(t + 1) * BB * HLL);
        dec_part_gemm<<<dim3(4, 8, DSPL), 256>>>(ph, dec_W, pdecp);
        dec_reduce<<<512, 256>>>(pdecp, dec_b, pdec);
        dec_split<<<BB * EE / 256, 256>>>(pdec);
        logits_mma<<<dim3(NBT, 4), 256>>>(kk0[t], kk1[t], pcandv, pcandi);
        sample_reduce<<<512, 256>>>(pcandv, pcandi, ptok,
                                    out + (size_t)t * BB);
    }

    gates_gemm<<<dim3(48, 8, 2), 256>>>(word_emb, ptok, w_ih, pgictx, pgi,
                                        ph, w_hh, b_hh, pgh);
    gru_act<<<2048, 256>>>(pgi, pgh, ph,
                           hsbase + (size_t)(TST + 1) * BB * HLL);

    (void)in_sizes; (void)n_in; (void)out_size;
}

// round 17
// speedup vs baseline: 1.2706x; 1.2706x over previous
#include <cuda_runtime.h>
#include <cuda_bf16.h>
#include <cstdint>

// Problem constants
#define VV   32000
#define EE   256
#define HLL  1024
#define HCC  256
#define BB   512
#define TST  100
#define DSPL 4        // dec split-K factor
#define NBT  250      // logits n-blocks (32000/128)

// ---------------- scratch (__device__ globals, no allocation) ----------------
__device__ float g_h[BB * HLL];
__device__ float g_gi[BB * 3 * HLL];
__device__ float g_gh[BB * 3 * HLL];
__device__ float g_gictx[BB * 3 * HLL];
__device__ float g_dec[BB * EE];
__device__ float g_decpart[DSPL * BB * EE];
__device__ __nv_bfloat16 g_e0[(size_t)VV * EE];
__device__ __nv_bfloat16 g_a0[BB * EE];
__device__ float g_decnorm[BB];
__device__ int   g_embmax;
__device__ float g_candv[BB * NBT];
__device__ int   g_tok[BB];

// ---------------- threefry2x32 ----------------
__host__ __device__ __forceinline__ unsigned int rotl32(unsigned int x, int r) {
    return (x << r) | (x >> (32 - r));
}
__host__ __device__ __forceinline__ void threefry2x32(
    unsigned int k0, unsigned int k1, unsigned int& x0, unsigned int& x1)
{
    unsigned int ks2 = k0 ^ k1 ^ 0x1BD11BDAu;
    x0 += k0; x1 += k1;
#define TF_R(r) { x0 += x1; x1 = rotl32(x1, (r)); x1 ^= x0; }
    TF_R(13) TF_R(15) TF_R(26) TF_R(6)   x0 += k1;  x1 += ks2 + 1u;
    TF_R(17) TF_R(29) TF_R(16) TF_R(24)  x0 += ks2; x1 += k0  + 2u;
    TF_R(13) TF_R(15) TF_R(26) TF_R(6)   x0 += k0;  x1 += k1  + 3u;
    TF_R(17) TF_R(29) TF_R(16) TF_R(24)  x0 += k1;  x1 += ks2 + 4u;
    TF_R(13) TF_R(15) TF_R(26) TF_R(6)   x0 += ks2; x1 += k0  + 5u;
#undef TF_R
}

// ---------------- flag-proof transcendentals ----------------
__device__ __forceinline__ float acc_logf(float a) {
    int e = (__float_as_int(a) - 0x3f2aaaab) & 0xff800000;
    float m = __int_as_float(__float_as_int(a) - e);
    float i = (float)e * 1.19209290e-7f;
    float f = m - 1.0f;
    float s = f * f;
    float r = fmaf(0.230836749f, f, -0.279208571f);
    float t = fmaf(0.331826031f, f, -0.498910338f);
    r = fmaf(r, s, t);
    r = fmaf(r, s, f);
    r = fmaf(i, 0.693147182f, r);
    return r;
}
__device__ __forceinline__ float acc_expf(float a) {
    float j = fmaf(1.442695041f, a, 12582912.0f) - 12582912.0f;
    float f = fmaf(j, -6.93145752e-1f, a);
    f = fmaf(j, -1.42860677e-6f, f);
    float r = 1.37805939e-3f;
    r = fmaf(r, f, 8.37312452e-3f);
    r = fmaf(r, f, 4.16695364e-2f);
    r = fmaf(r, f, 1.66664720e-1f);
    r = fmaf(r, f, 4.99999851e-1f);
    r = fmaf(r, f, 1.0f);
    r = fmaf(r, f, 1.0f);
    int i = (int)j;
    return r * __int_as_float((127 + i) << 23);
}
__device__ __forceinline__ float acc_sigmoid(float x) { return 1.0f / (1.0f + acc_expf(-x)); }
__device__ __forceinline__ float acc_tanh(float x) {
    float t = acc_expf(2.0f * x);
    return (t - 1.0f) / (t + 1.0f);
}
__device__ __forceinline__ float gumbel_from_bits(unsigned int bits) {
    float f = __uint_as_float((bits >> 9) | 0x3f800000u) - 1.0f;
    const float TINY = 1.17549435e-38f;
    float u = fmaxf(TINY, f + TINY);
    return -acc_logf(-acc_logf(u));
}

// ---------------- base-ISA MMA helpers ----------------
__device__ __forceinline__ uint32_t smem_to_u32(const void* p) {
    uint32_t a;
    asm("{ .reg .u64 t; cvta.to.shared.u64 t, %1; cvt.u32.u64 %0, t; }" : "=r"(a) : "l"(p));
    return a;
}
__device__ __forceinline__ void ldsm_x4(uint32_t& r0, uint32_t& r1,
                                        uint32_t& r2, uint32_t& r3, uint32_t addr)
{
    asm volatile("ldmatrix.sync.aligned.m8n8.x4.shared.b16 {%0,%1,%2,%3}, [%4];"
                 : "=r"(r0), "=r"(r1), "=r"(r2), "=r"(r3) : "r"(addr));
}
__device__ __forceinline__ void mma16816(float* d, const uint32_t* a,
                                         uint32_t b0, uint32_t b1)
{
    asm volatile(
        "mma.sync.aligned.m16n8k16.row.col.f32.bf16.bf16.f32 "
        "{%0,%1,%2,%3}, {%4,%5,%6,%7}, {%8,%9}, {%0,%1,%2,%3};"
        : "+f"(d[0]), "+f"(d[1]), "+f"(d[2]), "+f"(d[3])
        : "r"(a[0]), "r"(a[1]), "r"(a[2]), "r"(a[3]), "r"(b0), "r"(b1));
}

// ---------------- init ----------------
__global__ void init_kernel(const float* __restrict__ lang_h0,
                            const int* __restrict__ inpt0,
                            float* __restrict__ out)
{
    int idx = blockIdx.x * blockDim.x + threadIdx.x;
    if (idx < BB * HLL) {
        float v = lang_h0[idx];
        g_h[idx] = v;
        out[(size_t)TST * BB + idx] = v;
    }
    if (idx < BB) g_tok[idx] = inpt0[idx];
    if (idx == 0) g_embmax = 0;
}

// ---------------- emb prep: bf16 plane + max row norm (once) ----------------
__global__ void __launch_bounds__(256) emb_prep(const float* __restrict__ emb)
{
    int n = blockIdx.x;            // vocab row
    int tid = threadIdx.x;         // 256 = EE
    float v = emb[(size_t)n * EE + tid];
    g_e0[(size_t)n * EE + tid] = __float2bfloat16(v);
    __shared__ float red[256];
    red[tid] = v * v;
    __syncthreads();
    for (int s = 128; s > 0; s >>= 1) {
        if (tid < s) red[tid] += red[tid + s];
        __syncthreads();
    }
    if (tid == 0) {
        float nrm = sqrtf(red[0]) * 1.001f + 1e-8f;
        atomicMax(&g_embmax, __float_as_int(nrm));   // norms > 0: int cmp valid
    }
}

// ---------------- dec prep: bf16 plane + row norm (per step) ----------------
__global__ void __launch_bounds__(256) dec_split(const float* __restrict__ dec)
{
    int m = blockIdx.x;
    int tid = threadIdx.x;
    float v = dec[m * EE + tid];
    g_a0[m * EE + tid] = __float2bfloat16(v);
    __shared__ float red[256];
    red[tid] = v * v;
    __syncthreads();
    for (int s = 128; s > 0; s >>= 1) {
        if (tid < s) red[tid] += red[tid + s];
        __syncthreads();
    }
    if (tid == 0) g_decnorm[m] = sqrtf(red[0]) * 1.001f + 1e-8f;
}

// ============================================================================
// 64x64x16 double-buffered SGEMM core (FFMA; gates/dec/gictx)
// ============================================================================
#define GEMM64_BODY(A, LDA, AROW, BM, LDB, C, LDC, K, BIAS, ADDM, LDADD, M0, N0) \
{                                                                              \
    __shared__ float As[2][16 * 68];                                           \
    __shared__ float Bs[2][16 * 68];                                           \
    int tid = threadIdx.x;                                                     \
    int tx = tid & 15, ty = tid >> 4;                                          \
    int lr = tid >> 2;                                                         \
    int lk = (tid & 3) * 4;                                                    \
    int am_ = (AROW) ? (AROW)[(M0) + lr] : ((M0) + lr);                        \
    const float* aptr = (A) + (size_t)am_ * (LDA) + lk;                        \
    const float* bptr = (BM) + (size_t)((N0) + lr) * (LDB) + lk;               \
    float4 ra = *(const float4*)aptr;                                          \
    float4 rb = *(const float4*)bptr;                                          \
    As[0][(lk + 0) * 68 + lr] = ra.x; As[0][(lk + 1) * 68 + lr] = ra.y;        \
    As[0][(lk + 2) * 68 + lr] = ra.z; As[0][(lk + 3) * 68 + lr] = ra.w;        \
    Bs[0][(lk + 0) * 68 + lr] = rb.x; Bs[0][(lk + 1) * 68 + lr] = rb.y;        \
    Bs[0][(lk + 2) * 68 + lr] = rb.z; Bs[0][(lk + 3) * 68 + lr] = rb.w;        \
    __syncthreads();                                                           \
    float acc[4][4] = {};                                                      \
    int nkt = (K) / 16;                                                        \
    for (int kt = 0; kt < nkt; ++kt) {                                         \
        int cur = kt & 1;                                                      \
        if (kt + 1 < nkt) {                                                    \
            ra = *(const float4*)(aptr + (kt + 1) * 16);                       \
            rb = *(const float4*)(bptr + (kt + 1) * 16);                       \
        }                                                                      \
        _Pragma("unroll")                                                      \
        for (int k = 0; k < 16; ++k) {                                         \
            float4 a = *(const float4*)&As[cur][k * 68 + ty * 4];              \
            float4 b = *(const float4*)&Bs[cur][k * 68 + tx * 4];              \
            float av[4] = {a.x, a.y, a.z, a.w};                                \
            float bv[4] = {b.x, b.y, b.z, b.w};                                \
            _Pragma("unroll")                                                  \
            for (int i = 0; i < 4; ++i)                                        \
                _Pragma("unroll")                                              \
                for (int j = 0; j < 4; ++j)                                    \
                    acc[i][j] = fmaf(av[i], bv[j], acc[i][j]);                 \
        }                                                                      \
        if (kt + 1 < nkt) {                                                    \
            int nxt = cur ^ 1;                                                 \
            As[nxt][(lk + 0) * 68 + lr] = ra.x; As[nxt][(lk + 1) * 68 + lr] = ra.y; \
            As[nxt][(lk + 2) * 68 + lr] = ra.z; As[nxt][(lk + 3) * 68 + lr] = ra.w; \
            Bs[nxt][(lk + 0) * 68 + lr] = rb.x; Bs[nxt][(lk + 1) * 68 + lr] = rb.y; \
            Bs[nxt][(lk + 2) * 68 + lr] = rb.z; Bs[nxt][(lk + 3) * 68 + lr] = rb.w; \
        }                                                                      \
        __syncthreads();                                                       \
    }                                                                          \
    _Pragma("unroll")                                                          \
    for (int i = 0; i < 4; ++i) {                                              \
        int m = (M0) + ty * 4 + i;                                             \
        int n = (N0) + tx * 4;                                                 \
        float4 v = make_float4(acc[i][0], acc[i][1], acc[i][2], acc[i][3]);    \
        if (BIAS) {                                                            \
            float4 bb = *(const float4*)&(BIAS)[n];                            \
            v.x += bb.x; v.y += bb.y; v.z += bb.z; v.w += bb.w;                \
        }                                                                      \
        if (ADDM) {                                                            \
            float4 ad = *(const float4*)&(ADDM)[(size_t)m * (LDADD) + n];      \
            v.x += ad.x; v.y += ad.y; v.z += ad.z; v.w += ad.w;                \
        }                                                                      \
        *(float4*)&(C)[(size_t)m * (LDC) + n] = v;                             \
    }                                                                          \
}

__global__ void __launch_bounds__(256) gates_gemm(
    const float* __restrict__ word_emb, const int* __restrict__ tok,
    const float* __restrict__ w_ih, const float* __restrict__ gictx,
    float* __restrict__ gi,
    const float* __restrict__ h, const float* __restrict__ w_hh,
    const float* __restrict__ b_hh, float* __restrict__ gh)
{
    int m0 = blockIdx.y * 64, n0 = blockIdx.x * 64;
    if (blockIdx.z == 0) {
        GEMM64_BODY(word_emb, EE, tok, w_ih, (EE + HCC), gi, (3 * HLL), EE,
                    ((const float*)0), gictx, (3 * HLL), m0, n0);
    } else {
        GEMM64_BODY(h, HLL, ((const int*)0), w_hh, HLL, gh, (3 * HLL), HLL,
                    b_hh, ((const float*)0), 0, m0, n0);
    }
}

__global__ void __launch_bounds__(256) gictx_gemm(
    const float* __restrict__ ctx_h, const float* __restrict__ w_ih,
    const float* __restrict__ b_ih, float* __restrict__ gictx)
{
    int m0 = blockIdx.y * 64, n0 = blockIdx.x * 64;
    GEMM64_BODY(ctx_h, HCC, ((const int*)0), (w_ih + EE), (EE + HCC),
                gictx, (3 * HLL), HCC, b_ih, ((const float*)0), 0, m0, n0);
}

__global__ void __launch_bounds__(256) dec_part_gemm(
    const float* __restrict__ h, const float* __restrict__ dec_W,
    float* __restrict__ part)
{
    int m0 = blockIdx.y * 64, n0 = blockIdx.x * 64;
    int koff = blockIdx.z * (HLL / DSPL);
    const float* A = h + koff;
    const float* B = dec_W + koff;
    float* C = part + (size_t)blockIdx.z * BB * EE;
    GEMM64_BODY(A, HLL, ((const int*)0), B, HLL, C, EE, (HLL / DSPL),
                ((const float*)0), ((const float*)0), 0, m0, n0);
}

__global__ void dec_reduce(const float* __restrict__ part,
                           const float* __restrict__ dec_b,
                           float* __restrict__ dec)
{
    int idx = blockIdx.x * blockDim.x + threadIdx.x;
    float s = dec_b[idx & (EE - 1)];
#pragma unroll
    for (int z = 0; z < DSPL; ++z)
        s += part[(size_t)z * BB * EE + idx];
    dec[idx] = s;
}

// ============================================================================
// Pass 1: approx logits via single-plane bf16 HMMA + gumbel + per-block max.
// Grid (250, 4), 256 thr. CTA tile 128x128, K=256 in 8 chunks of 32.
// ============================================================================
__global__ void __launch_bounds__(256, 2) logits_approx(
    unsigned int k0, unsigned int k1, float* __restrict__ candv)
{
    __shared__ __nv_bfloat16 As[2][128 * 40];  // pitch 40 bf16 = 80 B
    __shared__ __nv_bfloat16 Bs[2][128 * 40];
    __shared__ float scv[2][128];

    int tid = threadIdx.x;
    int lane = tid & 31;
    int wid = tid >> 5;
    int warpm = wid >> 1;
    int warpn = wid & 1;
    int m0g = blockIdx.y * 128;
    int n0g = blockIdx.x * 128;
    int lrow = tid >> 2;
    int lq = tid & 3;

    const __nv_bfloat16* asrc0 = g_a0 + (size_t)m0g * EE;
    const __nv_bfloat16* bsrc0 = g_e0 + (size_t)n0g * EE;

    float acc[2][8][4];
#pragma unroll
    for (int mt = 0; mt < 2; ++mt)
#pragma unroll
        for (int nt = 0; nt < 8; ++nt)
#pragma unroll
            for (int r = 0; r < 4; ++r) acc[mt][nt][r] = 0.0f;

    uint4 ra0, ra1, rb0, rb1;
    ra0 = *(const uint4*)(asrc0 + (size_t)lrow * EE + lq * 8);
    ra1 = *(const uint4*)(asrc0 + (size_t)(lrow + 64) * EE + lq * 8);
    rb0 = *(const uint4*)(bsrc0 + (size_t)lrow * EE + lq * 8);
    rb1 = *(const uint4*)(bsrc0 + (size_t)(lrow + 64) * EE + lq * 8);
    *(uint4*)((char*)&As[0][0] + lrow * 80 + lq * 16) = ra0;
    *(uint4*)((char*)&As[0][0] + (lrow + 64) * 80 + lq * 16) = ra1;
    *(uint4*)((char*)&Bs[0][0] + lrow * 80 + lq * 16) = rb0;
    *(uint4*)((char*)&Bs[0][0] + (lrow + 64) * 80 + lq * 16) = rb1;
    __syncthreads();

    for (int c = 0; c < 8; ++c) {
        int cur = c & 1;
        if (c + 1 < 8) {
            int kk = (c + 1) * 32;
            ra0 = *(const uint4*)(asrc0 + (size_t)lrow * EE + kk + lq * 8);
            ra1 = *(const uint4*)(asrc0 + (size_t)(lrow + 64) * EE + kk + lq * 8);
            rb0 = *(const uint4*)(bsrc0 + (size_t)lrow * EE + kk + lq * 8);
            rb1 = *(const uint4*)(bsrc0 + (size_t)(lrow + 64) * EE + kk + lq * 8);
        }

        uint32_t a_base = smem_to_u32(&As[cur][0]);
        uint32_t b_base = smem_to_u32(&Bs[cur][0]);
#pragma unroll
        for (int ks = 0; ks < 2; ++ks) {
            uint32_t af[2][4];
#pragma unroll
            for (int mt = 0; mt < 2; ++mt) {
                int row = warpm * 32 + mt * 16 + (lane & 15);
                uint32_t ad = a_base + row * 80 + ks * 32 + ((lane >> 4) * 16);
                ldsm_x4(af[mt][0], af[mt][1], af[mt][2], af[mt][3], ad);
            }
#pragma unroll
            for (int p = 0; p < 4; ++p) {
                int row = warpn * 64 + p * 16 + (lane & 15);
                uint32_t bd = b_base + row * 80 + ks * 32 + ((lane >> 4) * 16);
                uint32_t r0, r1, r2, r3;
                ldsm_x4(r0, r1, r2, r3, bd);
#pragma unroll
                for (int mt = 0; mt < 2; ++mt) {
                    mma16816(acc[mt][2 * p], af[mt], r0, r2);
                    mma16816(acc[mt][2 * p + 1], af[mt], r1, r3);
                }
            }
        }

        if (c + 1 < 8) {
            int nxt = cur ^ 1;
            *(uint4*)((char*)&As[nxt][0] + lrow * 80 + lq * 16) = ra0;
            *(uint4*)((char*)&As[nxt][0] + (lrow + 64) * 80 + lq * 16) = ra1;
            *(uint4*)((char*)&Bs[nxt][0] + lrow * 80 + lq * 16) = rb0;
            *(uint4*)((char*)&Bs[nxt][0] + (lrow + 64) * 80 + lq * 16) = rb1;
        }
        __syncthreads();
    }

    // Epilogue: add gumbel, take per-row MAX over this block's 128 cols.
#pragma unroll
    for (int mt = 0; mt < 2; ++mt) {
#pragma unroll
        for (int rr = 0; rr < 2; ++rr) {
            int lrow_m = warpm * 32 + mt * 16 + rr * 8 + (lane >> 2);
            int gm = m0g + lrow_m;
            unsigned int jbase = (unsigned int)gm * (unsigned int)VV;
            float bv = -3.4e38f;
#pragma unroll
            for (int nt = 0; nt < 8; ++nt) {
#pragma unroll
                for (int jj = 0; jj < 2; ++jj) {
                    int n = n0g + warpn * 64 + nt * 8 + (lane & 3) * 2 + jj;
                    unsigned int x0 = 0u;
                    unsigned int x1 = jbase + (unsigned int)n;
                    threefry2x32(k0, k1, x0, x1);
                    float cval = acc[mt][nt][rr * 2 + jj] + gumbel_from_bits(x0 ^ x1);
                    bv = fmaxf(bv, cval);
                }
            }
#pragma unroll
            for (int s = 1; s < 4; s <<= 1)
                bv = fmaxf(bv, __shfl_xor_sync(0xffffffffu, bv, s));
            if ((lane & 3) == 0) scv[warpn][lrow_m] = bv;
        }
    }
    __syncthreads();
    if (tid < 128)
        candv[(size_t)(m0g + tid) * NBT + blockIdx.x] = fmaxf(scv[0][tid], scv[1][tid]);
}

// ============================================================================
// Pass 2: exact rescan of blocks within rigorous margin -> token.
// One block per batch row. 256 threads.
// ============================================================================
__global__ void __launch_bounds__(256) refine_kernel(
    const float* __restrict__ dec, const float* __restrict__ candv,
    const float* __restrict__ emb,
    unsigned int k0, unsigned int k1,
    int* __restrict__ tok, float* __restrict__ outtok)
{
    int m = blockIdx.x;
    int tid = threadIdx.x;
    __shared__ float sdec[256];
    __shared__ float scand[NBT];
    __shared__ float red[256];
    __shared__ float colv[128];
    __shared__ float brv[128];
    __shared__ int   bri[128];

    sdec[tid] = dec[m * EE + tid];
    for (int b = tid; b < NBT; b += 256) scand[b] = candv[(size_t)m * NBT + b];
    __syncthreads();

    float v = -3.4e38f;
    for (int b = tid; b < NBT; b += 256) v = fmaxf(v, scand[b]);
    red[tid] = v;
    __syncthreads();
    for (int s = 128; s > 0; s >>= 1) {
        if (tid < s) red[tid] = fmaxf(red[tid], red[tid + s]);
        __syncthreads();
    }
    float T = red[0];
    float embmax = __int_as_float(g_embmax);
    // rigorous bf16 bound ~2.01*2^-9*|dec||emb|; use 2^-7 (4x safety) + abs eps
    float delta = 0.0078125f * g_decnorm[m] * embmax + 1e-5f;
    float tau = T - 2.0f * delta;
    unsigned int jbase = (unsigned int)m * (unsigned int)VV;

    float best = -3.4e38f;
    int bestn = VV;
    for (int b = 0; b < NBT; ++b) {
        if (scand[b] < tau) continue;     // block-uniform branch
        int col = tid >> 1;
        int half = tid & 1;
        int n = b * 128 + col;
        const float* er = emb + (size_t)n * EE + half * 128;
        const float* dr = sdec + half * 128;
        float s = 0.0f;
#pragma unroll 8
        for (int k = 0; k < 128; ++k) s = fmaf(dr[k], er[k], s);
        float oth = __shfl_xor_sync(0xffffffffu, s, 1);
        if (half == 0) {
            float tot = s + oth;          // fixed order: low half + high half
            unsigned int x0 = 0u;
            unsigned int x1 = jbase + (unsigned int)n;
            threefry2x32(k0, k1, x0, x1);
            colv[col] = tot + gumbel_from_bits(x0 ^ x1);
        }
        __syncthreads();
        if (tid < 128) { brv[tid] = colv[tid]; bri[tid] = b * 128 + tid; }
        __syncthreads();
        for (int sr = 64; sr > 0; sr >>= 1) {
            if (tid < sr) {
                float v2 = brv[tid + sr]; int i2 = bri[tid + sr];
                if (v2 > brv[tid] || (v2 == brv[tid] && i2 < bri[tid])) {
                    brv[tid] = v2; bri[tid] = i2;
                }
            }
            __syncthreads();
        }
        if (tid == 0) {
            if (brv[0] > best || (brv[0] == best && bri[0] < bestn)) {
                best = brv[0]; bestn = bri[0];
            }
        }
        __syncthreads();
    }
    if (tid == 0) {
        tok[m] = bestn;
        outtok[m] = (float)bestn;
    }
}

// ---------------- GRU elementwise ----------------
__global__ void gru_act(const float* __restrict__ gi, const float* __restrict__ gh,
                        float* __restrict__ h, float* __restrict__ hs_out)
{
    int idx = blockIdx.x * blockDim.x + threadIdx.x;
    int b = idx >> 10, j = idx & 1023;
    size_t base = (size_t)b * 3072 + j;
    float ir = gi[base], iz = gi[base + 1024], in_ = gi[base + 2048];
    float hr = gh[base], hz = gh[base + 1024], hn = gh[base + 2048];
    float r = acc_sigmoid(ir + hr);
    float z = acc_sigmoid(iz + hz);
    float n = acc_tanh(in_ + r * hn);
    float hprev = h[idx];
    float hnew = (1.0f - z) * n + z * hprev;
    h[idx] = hnew;
    hs_out[idx] = hnew;
}

// ---------------- host driver ----------------
extern "C" void kernel_launch(void* const* d_in, const int* in_sizes, int n_in,
                              void* d_out, int out_size)
{
    const float* lang_h0  = (const float*)d_in[0];
    const float* ctx_h    = (const float*)d_in[1];
    const float* word_emb = (const float*)d_in[2];
    const float* dec_W    = (const float*)d_in[3];
    const float* dec_b    = (const float*)d_in[4];
    const float* w_ih     = (const float*)d_in[5];
    const float* w_hh     = (const float*)d_in[6];
    const float* b_ih     = (const float*)d_in[7];
    const float* b_hh     = (const float*)d_in[8];
    const int*   inpt0    = (const int*)d_in[9];
    float* out = (float*)d_out;

    float *ph, *pgi, *pgh, *pgictx, *pdec, *pdecp, *pcandv;
    int *ptok;
    cudaGetSymbolAddress((void**)&ph, g_h);
    cudaGetSymbolAddress((void**)&pgi, g_gi);
    cudaGetSymbolAddress((void**)&pgh, g_gh);
    cudaGetSymbolAddress((void**)&pgictx, g_gictx);
    cudaGetSymbolAddress((void**)&pdec, g_dec);
    cudaGetSymbolAddress((void**)&pdecp, g_decpart);
    cudaGetSymbolAddress((void**)&pcandv, g_candv);
    cudaGetSymbolAddress((void**)&ptok, g_tok);

    // PARTITIONABLE key schedule: key_t = threefry2x32(key=(0,1), 0, t)
    unsigned int kk0[TST], kk1[TST];
    for (int t = 0; t < TST; ++t) {
        unsigned int x0 = 0u, x1 = (unsigned int)t;
        threefry2x32(0u, 1u, x0, x1);
        kk0[t] = x0;
        kk1[t] = x1;
    }

    init_kernel<<<2048, 256>>>(lang_h0, inpt0, out);
    emb_prep<<<VV, 256>>>(word_emb);
    gictx_gemm<<<dim3(48, 8), 256>>>(ctx_h, w_ih, b_ih, pgictx);

    float* hsbase = out + (size_t)TST * BB;

    for (int t = 0; t < TST; ++t) {
        gates_gemm<<<dim3(48, 8, 2), 256>>>(word_emb, ptok, w_ih, pgictx, pgi,
                                            ph, w_hh, b_hh, pgh);
        gru_act<<<2048, 256>>>(pgi, pgh, ph,
                               hsbase + (size_t)(t + 1) * BB * HLL);
        dec_part_gemm<<<dim3(4, 8, DSPL), 256>>>(ph, dec_W, pdecp);
        dec_reduce<<<512, 256>>>(pdecp, dec_b, pdec);
        dec_split<<<BB, 256>>>(pdec);
        logits_approx<<<dim3(NBT, 4), 256>>>(kk0[t], kk1[t], pcandv);
        refine_kernel<<<BB, 256>>>(pdec, pcandv, word_emb, kk0[t], kk1[t],
                                   ptok, out + (size_t)t * BB);
    }

    gates_gemm<<<dim3(48, 8, 2), 256>>>(word_emb, ptok, w_ih, pgictx, pgi,
                                        ph, w_hh, b_hh, pgh);
    gru_act<<<2048, 256>>>(pgi, pgh, ph,
                           hsbase + (size_t)(TST + 1) * BB * HLL);

    (void)in_sizes; (void)n_in; (void)out_size;
}